// round 3
// baseline (speedup 1.0000x reference)
#include <cuda_runtime.h>
#include <cuda_bf16.h>

#define MCTA 32
#define NCTAS 64
#define NTHREADS 512
#define NWARPS 16
#define T_STEPS 128
#define KSTEPS 17
#define ACT_STRIDE 280   // bf16 elems per row

// Packed weights: [tile][kstep][lane] as uint2 (4 bf16 = one B-fragment lane slice)
// GEMM1 (Wm0): tiles 0..31 ; GEMM2 (Wf10|Wf20|Wh0): 32..127 ; GEMM3 (Wm1): 128..159
__device__ uint2 g_Wpk[160 * 17 * 32];
__device__ float4 g_smallW4[768];

#define G1_OFF 0
#define G2_OFF (32 * 17 * 32)
#define G3_OFF (128 * 17 * 32)

// ---------------------------------------------------------------------------
// Unified activation column layout (padded K = 272):
//   0..255  : c / cu / c_new (phase dependent)
//   256..257: m2 = meas/60           (written each step in P2)
//   258..261: s/60 (= su/60 after update; equals next step's sn!)  (written P4)
//   262..271: always zero
// Weight row remap into padded columns:
//   type 0 (Wm0,Wf10,Wf20; fin=260): rows 0..255 -> cols 0..255, rows 256..259 -> cols 258..261
//   type 1 (Wh0; fin=262):           rows 0..255 -> 0..255, rows 260..261 -> 256..257, rows 256..259 -> 258..261
//   type 2 (Wm1; fin=262):           identity (cu | m2 | su/60)
// ---------------------------------------------------------------------------
__global__ void prepack_kernel(
    const float* __restrict__ Wm0, const float* __restrict__ Wf10,
    const float* __restrict__ Wf20, const float* __restrict__ Wh0,
    const float* __restrict__ Wm1, const float* __restrict__ Wf11,
    const float* __restrict__ Wf21, const float* __restrict__ Wh1)
{
    const int total_u32 = 160 * 17 * 32 * 2;
    int idx = blockIdx.x * blockDim.x + threadIdx.x;
    if (idx < total_u32) {
        int r    = idx & 1;
        int lane = (idx >> 1) & 31;
        int tk   = idx >> 6;          // tile*17 + ks
        int ks   = tk % 17;
        int tile = tk / 17;
        int kk = ks * 16 + (lane & 3) * 2 + r * 8;
        const float* W; int type; int ncol;
        if (tile < 32) {
            W = Wm0; type = 0; ncol = tile * 8 + (lane >> 2);
        } else if (tile < 128) {
            int n2 = (tile - 32) * 8 + (lane >> 2);
            if (n2 < 256)      { W = Wf10; type = 0; ncol = n2; }
            else if (n2 < 512) { W = Wf20; type = 0; ncol = n2 - 256; }
            else               { W = Wh0;  type = 1; ncol = n2 - 512; }
        } else {
            W = Wm1; type = 2; ncol = (tile - 128) * 8 + (lane >> 2);
        }
        auto srcrow = [&](int k) -> int {
            if (type == 0) return k < 256 ? k : ((k >= 258 && k < 262) ? k - 2 : -1);
            if (type == 1) return k < 256 ? k : (k < 258 ? k + 4 : (k < 262 ? k - 2 : -1));
            return k < 262 ? k : -1;
        };
        int s0 = srcrow(kk), s1 = srcrow(kk + 1);
        float v0 = (s0 >= 0) ? W[(size_t)s0 * 256 + ncol] : 0.f;
        float v1 = (s1 >= 0) ? W[(size_t)s1 * 256 + ncol] : 0.f;
        __nv_bfloat162 p;
        p.x = __float2bfloat16(v0);
        p.y = __float2bfloat16(v1);
        reinterpret_cast<unsigned*>(g_Wpk)[idx] = *reinterpret_cast<unsigned*>(&p);
    } else if (idx < total_u32 + 768) {
        int j = idx - total_u32;
        float4 v = make_float4(0.f, 0.f, 0.f, 0.f);
        if (j < 256)      { v.x = Wf11[j * 2];        v.y = Wf11[j * 2 + 1]; }
        else if (j < 512) { int q = j - 256;
                            v.x = Wf21[q * 4]; v.y = Wf21[q * 4 + 1];
                            v.z = Wf21[q * 4 + 2]; v.w = Wf21[q * 4 + 3]; }
        else              { int q = j - 512;
                            v.x = Wh1[q * 2];  v.y = Wh1[q * 2 + 1]; }
        g_smallW4[j] = v;
    }
}

// ---------------------------------------------------------------------------
// Device helpers
// ---------------------------------------------------------------------------
__device__ __forceinline__ void mma16816(float* d, const unsigned* a, uint2 b) {
    asm volatile(
        "mma.sync.aligned.m16n8k16.row.col.f32.bf16.bf16.f32 "
        "{%0,%1,%2,%3}, {%4,%5,%6,%7}, {%8,%9}, {%0,%1,%2,%3};\n"
        : "+f"(d[0]), "+f"(d[1]), "+f"(d[2]), "+f"(d[3])
        : "r"(a[0]), "r"(a[1]), "r"(a[2]), "r"(a[3]), "r"(b.x), "r"(b.y));
}
__device__ __forceinline__ void ldmA(unsigned* a, unsigned addr) {
    asm volatile(
        "ldmatrix.sync.aligned.m8n8.x4.shared.b16 {%0,%1,%2,%3}, [%4];\n"
        : "=r"(a[0]), "=r"(a[1]), "=r"(a[2]), "=r"(a[3]) : "r"(addr));
}
__device__ __forceinline__ float tanha(float x) {
    float y; asm("tanh.approx.f32 %0, %1;" : "=f"(y) : "f"(x)); return y;
}

// 2-Mtile GEMM, NT N-tiles; last (NT-NFULL) tiles skip the final kstep.
// B-fragment prefetch distance 2 (ping-pong slot reload after consumption).
template <int NT, int NFULL>
__device__ __forceinline__ void run_gemm_m2(const uint2* const (&wp)[NT],
                                            unsigned ab0, unsigned ab1,
                                            float (&D)[NT][2][4]) {
    unsigned a0[4], a1[4], a0n[4], a1n[4];
    uint2 b[NT][2];
#pragma unroll
    for (int i = 0; i < NT; i++) { b[i][0] = wp[i][0]; b[i][1] = wp[i][32]; }
    ldmA(a0, ab0);
    ldmA(a1, ab1);
#pragma unroll 1
    for (int ks = 0; ks < KSTEPS; ks++) {
        const int cur = ks & 1;
        int ksn = (ks + 1 < KSTEPS) ? ks + 1 : ks;
        ldmA(a0n, ab0 + (unsigned)ksn * 32u);
        ldmA(a1n, ab1 + (unsigned)ksn * 32u);
        bool last = (ks == KSTEPS - 1);
#pragma unroll
        for (int i = 0; i < NT; i++) {
            if (i < NFULL || !last) {
                mma16816(D[i][0], a0, b[i][cur]);
                mma16816(D[i][1], a1, b[i][cur]);
            }
        }
        if (ks + 2 < KSTEPS) {
#pragma unroll
            for (int i = 0; i < NT; i++) b[i][cur] = wp[i][(ks + 2) * 32];
        }
#pragma unroll
        for (int q = 0; q < 4; q++) { a0[q] = a0n[q]; a1[q] = a1n[q]; }
    }
}

__device__ __forceinline__ void write_act_tanh(int ntile, int cbase, int row0,
        const float (&D)[2][4], const float* __restrict__ bias,
        __nv_bfloat16 (*actp)[ACT_STRIDE]) {
    int col = ntile * 8 + cbase;
    float bv0 = bias[col], bv1 = bias[col + 1];
#pragma unroll
    for (int m = 0; m < 2; m++) {
        __nv_bfloat162 h0, h1;
        h0.x = __float2bfloat16(tanha(D[m][0] + bv0));
        h0.y = __float2bfloat16(tanha(D[m][1] + bv1));
        h1.x = __float2bfloat16(tanha(D[m][2] + bv0));
        h1.y = __float2bfloat16(tanha(D[m][3] + bv1));
        *reinterpret_cast<__nv_bfloat162*>(&actp[m * 16 + row0][col]) = h0;
        *reinterpret_cast<__nv_bfloat162*>(&actp[m * 16 + row0 + 8][col]) = h1;
    }
}

// tanh + tiny second-layer products, accumulated into o[4 rowslots][8 outputs]
__device__ __forceinline__ void g2_epilogue(int tg, int cbase,
        const float (&D)[2][4], const float* __restrict__ bias2s,
        float (&o)[4][8]) {
    int col = tg * 8 + cbase;
    int seg = tg >> 5;  // 0: Wf11 (d), 1: Wf21 (pv), 2: Wh1 (hv)
    float bb0 = bias2s[col], bb1 = bias2s[col + 1];
    float4 w0 = g_smallW4[col];
    float4 w1 = g_smallW4[col + 1];
    int ob = (seg == 0) ? 0 : ((seg == 1) ? 2 : 6);
#pragma unroll
    for (int m = 0; m < 2; m++) {
        float h0 = tanha(D[m][0] + bb0);
        float h1 = tanha(D[m][1] + bb1);
        float h2 = tanha(D[m][2] + bb0);
        float h3 = tanha(D[m][3] + bb1);
        o[m*2+0][ob+0] += h0 * w0.x + h1 * w1.x;
        o[m*2+0][ob+1] += h0 * w0.y + h1 * w1.y;
        o[m*2+1][ob+0] += h2 * w0.x + h3 * w1.x;
        o[m*2+1][ob+1] += h2 * w0.y + h3 * w1.y;
        if (seg == 1) {
            o[m*2+0][ob+2] += h0 * w0.z + h1 * w1.z;
            o[m*2+0][ob+3] += h0 * w0.w + h1 * w1.w;
            o[m*2+1][ob+2] += h2 * w0.z + h3 * w1.z;
            o[m*2+1][ob+3] += h2 * w0.w + h3 * w1.w;
        }
    }
}

__device__ __forceinline__ void reduce_store(float (&o)[4][8],
        float (*partw)[9], int lane, int row0, bool add) {
#pragma unroll
    for (int s = 0; s < 4; s++)
#pragma unroll
        for (int k = 0; k < 8; k++) {
            o[s][k] += __shfl_xor_sync(0xffffffffu, o[s][k], 1);
            o[s][k] += __shfl_xor_sync(0xffffffffu, o[s][k], 2);
        }
    if ((lane & 3) == 0) {
#pragma unroll
        for (int s = 0; s < 4; s++) {
            float* p = partw[row0 + s * 8];
#pragma unroll
            for (int k = 0; k < 8; k++)
                p[k] = add ? (p[k] + o[s][k]) : o[s][k];
        }
    }
}

// ---------------------------------------------------------------------------
// Main persistent kernel: 64 CTAs x 512 threads, 32 batch rows per CTA.
// ---------------------------------------------------------------------------
__global__ void __launch_bounds__(NTHREADS, 1) egbrnn_main(
    const float* __restrict__ x, const float* __restrict__ target,
    const float* __restrict__ c0,
    const float* __restrict__ bm0, const float* __restrict__ bm1,
    const float* __restrict__ bf10, const float* __restrict__ bf11,
    const float* __restrict__ bf20, const float* __restrict__ bf21,
    const float* __restrict__ bh0, const float* __restrict__ bh1,
    float* __restrict__ out)
{
    __shared__ __align__(16) __nv_bfloat16 act[MCTA][ACT_STRIDE];
    __shared__ float sS[MCTA][4];
    __shared__ float Pm[MCTA][16];
    __shared__ float measS[MCTA][2];
    __shared__ float part[NWARPS][MCTA][9];   // pad 9: conflict-free column read
    __shared__ float bm0s[256], bm1s[256], bias2s[768], biasSs[8];

    const int tid = threadIdx.x;
    const int w = tid >> 5, lane = tid & 31;
    const int b0 = blockIdx.x * MCTA;
    const int row0 = lane >> 2;
    const int cbase = (lane & 3) * 2;

    // ---- one-time shared init ----
    if (tid < 256) { bm0s[tid] = bm0[tid]; bm1s[tid] = bm1[tid]; }
    for (int i = tid; i < 768; i += NTHREADS)
        bias2s[i] = (i < 256) ? bf10[i] : (i < 512 ? bf20[i - 256] : bh0[i - 512]);
    if (tid < 8)
        biasSs[tid] = (tid < 2) ? bf11[tid] : (tid < 6 ? bf21[tid - 2] : bh1[tid - 6]);
    for (int i = tid; i < MCTA * 18; i += NTHREADS) {   // zero cols 262..279
        int r = i / 18, c = 262 + i % 18;
        act[r][c] = __float2bfloat16(0.f);
    }
    for (int i = tid; i < MCTA * 256; i += NTHREADS) {  // c = c0
        int r = i >> 8, j = i & 255;
        act[r][j] = __float2bfloat16(c0[(size_t)(b0 + r) * 256 + j]);
    }
    if (tid < MCTA) {
        int r = tid;
        float4 tg = *reinterpret_cast<const float4*>(
            &target[((size_t)(b0 + r) * T_STEPS) * 4]);
        sS[r][0] = tg.x; sS[r][1] = tg.y; sS[r][2] = tg.z; sS[r][3] = tg.w;
#pragma unroll
        for (int i = 0; i < 16; i++) Pm[r][i] = (i % 5 == 0) ? 1.f : 0.f;
        __nv_bfloat162 z2; z2.x = __float2bfloat16(0.f); z2.y = z2.x;
        *reinterpret_cast<__nv_bfloat162*>(&act[r][256]) = z2;   // m2 slot
        __nv_bfloat162 a01, a23;
        a01.x = __float2bfloat16(tg.x * (1.f / 60.f));
        a01.y = __float2bfloat16(tg.y * (1.f / 60.f));
        a23.x = __float2bfloat16(tg.z * (1.f / 60.f));
        a23.y = __float2bfloat16(tg.w * (1.f / 60.f));
        *reinterpret_cast<__nv_bfloat162*>(&act[r][258]) = a01;  // s/60
        *reinterpret_cast<__nv_bfloat162*>(&act[r][260]) = a23;
    }
    __syncthreads();

    const unsigned ab0 =
        (unsigned)__cvta_generic_to_shared(&act[lane & 15][(lane >> 4) * 8]);
    const unsigned ab1 = ab0 + 16u * ACT_STRIDE * 2u;
    const uint2* w1p0 = g_Wpk + G1_OFF + (2 * w) * KSTEPS * 32 + lane;
    const uint2* w1p1 = w1p0 + KSTEPS * 32;
    const uint2* w2p  = g_Wpk + G2_OFF + (6 * w) * KSTEPS * 32 + lane;
    const uint2* w3p0 = g_Wpk + G3_OFF + (2 * w) * KSTEPS * 32 + lane;
    const uint2* w3p1 = w3p0 + KSTEPS * 32;

    for (int t = 0; t < T_STEPS; t++) {
        // ---- P1: GEMM1 (cu preactivation) ----
        float D1[2][2][4];
#pragma unroll
        for (int i = 0; i < 2; i++)
#pragma unroll
            for (int m = 0; m < 2; m++)
                D1[i][m][0] = D1[i][m][1] = D1[i][m][2] = D1[i][m][3] = 0.f;
        {
            const uint2* wp[2] = {w1p0, w1p1};
            run_gemm_m2<2, 2>(wp, ab0, ab1, D1);
        }
        __syncthreads();

        // ---- P2: write cu over c; load meas; write m2 ----
        write_act_tanh(2 * w,     cbase, row0, D1[0], bm0s, act);
        write_act_tanh(2 * w + 1, cbase, row0, D1[1], bm0s, act);
        if (tid < MCTA) {
            int r = tid;
            float m0 = x[(((size_t)(b0 + r)) * T_STEPS + t) * 2 + 0];
            float m1 = x[(((size_t)(b0 + r)) * T_STEPS + t) * 2 + 1];
            measS[r][0] = m0; measS[r][1] = m1;
            __nv_bfloat162 mm;
            mm.x = __float2bfloat16(m0 * (1.f / 60.f));
            mm.y = __float2bfloat16(m1 * (1.f / 60.f));
            *reinterpret_cast<__nv_bfloat162*>(&act[r][256]) = mm;
        }
        __syncthreads();

        // ---- P3: fused GEMM2 + GEMM3[ksteps 0..15] ----
        uint2 b3last0 = w3p0[16 * 32], b3last1 = w3p1[16 * 32];  // G3b frags
        float DB[4][2][4];
        {   // group A: 4 GEMM2 tiles
            float DA[4][2][4];
#pragma unroll
            for (int i = 0; i < 4; i++)
#pragma unroll
                for (int m = 0; m < 2; m++)
                    DA[i][m][0] = DA[i][m][1] = DA[i][m][2] = DA[i][m][3] = 0.f;
            const uint2* wp[4] = {w2p, w2p + KSTEPS * 32,
                                  w2p + 2 * KSTEPS * 32, w2p + 3 * KSTEPS * 32};
            run_gemm_m2<4, 4>(wp, ab0, ab1, DA);
            float o[4][8];
#pragma unroll
            for (int s = 0; s < 4; s++)
#pragma unroll
                for (int k = 0; k < 8; k++) o[s][k] = 0.f;
            g2_epilogue(6 * w + 0, cbase, DA[0], bias2s, o);
            g2_epilogue(6 * w + 1, cbase, DA[1], bias2s, o);
            g2_epilogue(6 * w + 2, cbase, DA[2], bias2s, o);
            g2_epilogue(6 * w + 3, cbase, DA[3], bias2s, o);
            reduce_store(o, part[w], lane, row0, false);
        }
        {   // group B: 2 GEMM2 tiles + 2 GEMM3 tiles (G3 skips kstep 16)
#pragma unroll
            for (int i = 0; i < 4; i++)
#pragma unroll
                for (int m = 0; m < 2; m++)
                    DB[i][m][0] = DB[i][m][1] = DB[i][m][2] = DB[i][m][3] = 0.f;
            const uint2* wp[4] = {w2p + 4 * KSTEPS * 32, w2p + 5 * KSTEPS * 32,
                                  w3p0, w3p1};
            run_gemm_m2<4, 2>(wp, ab0, ab1, DB);
            float o[4][8];
#pragma unroll
            for (int s = 0; s < 4; s++)
#pragma unroll
                for (int k = 0; k < 8; k++) o[s][k] = 0.f;
            g2_epilogue(6 * w + 4, cbase, DB[0], bias2s, o);
            g2_epilogue(6 * w + 5, cbase, DB[1], bias2s, o);
            reduce_store(o, part[w], lane, row0, true);
        }
        __syncthreads();

        // ---- P4: per-row Kalman update (fp32) ----
        if (tid < MCTA) {
            const int r = tid;
            float sm[8];
#pragma unroll
            for (int o = 0; o < 8; o++) {
                float a = biasSs[o];
#pragma unroll
                for (int ww = 0; ww < NWARPS; ww++) a += part[ww][r][o];
                sm[o] = a;
            }
            const float d0 = sm[0], d1 = sm[1];
            const float pv[4] = {sm[2], sm[3], sm[4], sm[5]};
            const float hv0 = sm[6], hv1 = sm[7];
            float s0 = sS[r][0], s1 = sS[r][1], s2 = sS[r][2], s3 = sS[r][3];
            float sp[4];
            sp[0] = s0 + s2 + 0.5f * d0;
            sp[1] = s1 + s3 + 0.5f * d1;
            sp[2] = s2 + d0;
            sp[3] = s3 + d1;
            float P[4][4];
#pragma unroll
            for (int i = 0; i < 4; i++)
#pragma unroll
                for (int j = 0; j < 4; j++) P[i][j] = Pm[r][i * 4 + j];
            float FP[4][4], Pp[4][4];
#pragma unroll
            for (int j = 0; j < 4; j++) {
                FP[0][j] = P[0][j] + P[2][j];
                FP[1][j] = P[1][j] + P[3][j];
                FP[2][j] = P[2][j];
                FP[3][j] = P[3][j];
            }
#pragma unroll
            for (int i = 0; i < 4; i++) {
                Pp[i][0] = FP[i][0] + FP[i][2];
                Pp[i][1] = FP[i][1] + FP[i][3];
                Pp[i][2] = FP[i][2];
                Pp[i][3] = FP[i][3];
            }
#pragma unroll
            for (int i = 0; i < 4; i++)
#pragma unroll
                for (int j = 0; j < 4; j++) Pp[i][j] += pv[i] * pv[j];
#pragma unroll
            for (int i = 0; i < 4; i++) Pp[i][i] += 0.01f;
            float m0 = measS[r][0], m1 = measS[r][1];
            float in0 = m0 - sp[0], in1 = m1 - sp[1];
            float S00 = Pp[0][0] + hv0 * hv0 + 1.f;
            float S01 = Pp[0][1] + hv0 * hv1;
            float S10 = Pp[1][0] + hv1 * hv0;
            float S11 = Pp[1][1] + hv1 * hv1 + 1.f;
            float inv = 1.0f / (S00 * S11 - S01 * S10);
            float K[4][2], KS[4][2], su[4];
#pragma unroll
            for (int i = 0; i < 4; i++) {
                K[i][0] = (Pp[i][0] * S11 - Pp[i][1] * S10) * inv;
                K[i][1] = (Pp[i][1] * S00 - Pp[i][0] * S01) * inv;
                su[i] = sp[i] + K[i][0] * in0 + K[i][1] * in1;
                KS[i][0] = K[i][0] * S00 + K[i][1] * S10;
                KS[i][1] = K[i][0] * S01 + K[i][1] * S11;
            }
#pragma unroll
            for (int i = 0; i < 4; i++)
#pragma unroll
                for (int j = 0; j < 4; j++)
                    Pm[r][i * 4 + j] =
                        Pp[i][j] - KS[i][0] * K[j][0] - KS[i][1] * K[j][1];
            sS[r][0] = su[0]; sS[r][1] = su[1];
            sS[r][2] = su[2]; sS[r][3] = su[3];
            float4 ov = make_float4(su[0], su[1], su[2], su[3]);
            *reinterpret_cast<float4*>(
                &out[(((size_t)(b0 + r)) * T_STEPS + t) * 4]) = ov;
            __nv_bfloat162 q0, q1;
            q0.x = __float2bfloat16(su[0] * (1.f / 60.f));
            q0.y = __float2bfloat16(su[1] * (1.f / 60.f));
            q1.x = __float2bfloat16(su[2] * (1.f / 60.f));
            q1.y = __float2bfloat16(su[3] * (1.f / 60.f));
            *reinterpret_cast<__nv_bfloat162*>(&act[r][258]) = q0;  // su/60 == next sn
            *reinterpret_cast<__nv_bfloat162*>(&act[r][260]) = q1;
        }
        __syncthreads();

        // ---- P5: GEMM3 final kstep (reads tail 256..271) + c_new epilogue
        //          (writes cols 0..255 only — disjoint from P5 reads) ----
        {
            unsigned a0[4], a1[4];
            ldmA(a0, ab0 + 16u * 32u);
            ldmA(a1, ab1 + 16u * 32u);
            mma16816(DB[2][0], a0, b3last0);
            mma16816(DB[2][1], a1, b3last0);
            mma16816(DB[3][0], a0, b3last1);
            mma16816(DB[3][1], a1, b3last1);
        }
        write_act_tanh(2 * w,     cbase, row0, DB[2], bm1s, act);
        write_act_tanh(2 * w + 1, cbase, row0, DB[3], bm1s, act);
        __syncthreads();
    }
}

// ---------------------------------------------------------------------------
extern "C" void kernel_launch(void* const* d_in, const int* in_sizes, int n_in,
                              void* d_out, int out_size)
{
    const float* x    = (const float*)d_in[0];
    const float* targ = (const float*)d_in[1];
    const float* c0   = (const float*)d_in[2];
    const float* Wm0  = (const float*)d_in[3];
    const float* bm0  = (const float*)d_in[4];
    const float* Wm1  = (const float*)d_in[5];
    const float* bm1  = (const float*)d_in[6];
    const float* Wf10 = (const float*)d_in[7];
    const float* bf10 = (const float*)d_in[8];
    const float* Wf11 = (const float*)d_in[9];
    const float* bf11 = (const float*)d_in[10];
    const float* Wf20 = (const float*)d_in[11];
    const float* bf20 = (const float*)d_in[12];
    const float* Wf21 = (const float*)d_in[13];
    const float* bf21 = (const float*)d_in[14];
    const float* Wh0  = (const float*)d_in[15];
    const float* bh0  = (const float*)d_in[16];
    const float* Wh1  = (const float*)d_in[17];
    const float* bh1  = (const float*)d_in[18];
    float* out = (float*)d_out;

    const int tot = 160 * 17 * 32 * 2 + 768;
    prepack_kernel<<<(tot + 255) / 256, 256>>>(Wm0, Wf10, Wf20, Wh0, Wm1,
                                               Wf11, Wf21, Wh1);
    egbrnn_main<<<NCTAS, NTHREADS>>>(x, targ, c0, bm0, bm1, bf10, bf11,
                                     bf20, bf21, bh0, bh1, out);
}

// round 4
// speedup vs baseline: 1.0718x; 1.0718x over previous
#include <cuda_runtime.h>
#include <cuda_bf16.h>

#define MCTA 16
#define NCTAS 128
#define NTHREADS 512
#define NWARPS 16
#define T_STEPS 128
#define KSTEPS 17
#define DEPTH 3
#define ACT_STRIDE 280   // bf16 elems per row

// Packed weights, fragment order. Tile map:
//   T in [0,32):    GEMM1 (Wm0), warp w owns T = 2w, 2w+1 (N cols [16w,16w+16))
//   T in [32,160):  per-warp P3 block: q=T-32, w=q/8, j=q%8
//                   j<6  -> GEMM2 tile tg=(6w+j)  (Wf10|Wf20|Wh0 over n2=8*tg)
//                   j>=6 -> GEMM3 (Wm1) n-tile 2w+(j-6)
__device__ uint2 g_Wpk[160 * 17 * 32];
__device__ float4 g_smallW4[768];

// ---------------------------------------------------------------------------
// Activation column layout (padded K = 272):
//   0..255: c / cu / c_new    256..257: meas/60    258..261: s/60   262..271: 0
// Row remap: type0 (Wm0,Wf10,Wf20;fin260): k<256->k, 258..261->k-2
//            type1 (Wh0;fin262): k<256->k, 256,257->k+4, 258..261->k-2
//            type2 (Wm1;fin262): identity
// ---------------------------------------------------------------------------
__global__ void prepack_kernel(
    const float* __restrict__ Wm0, const float* __restrict__ Wf10,
    const float* __restrict__ Wf20, const float* __restrict__ Wh0,
    const float* __restrict__ Wm1, const float* __restrict__ Wf11,
    const float* __restrict__ Wf21, const float* __restrict__ Wh1)
{
    const int total_u32 = 160 * 17 * 32 * 2;
    int idx = blockIdx.x * blockDim.x + threadIdx.x;
    if (idx < total_u32) {
        int r    = idx & 1;
        int lane = (idx >> 1) & 31;
        int tk   = idx >> 6;          // tile*17 + ks
        int ks   = tk % 17;
        int tile = tk / 17;
        int kk = ks * 16 + (lane & 3) * 2 + r * 8;
        const float* W; int type; int ncol;
        if (tile < 32) {
            W = Wm0; type = 0; ncol = tile * 8 + (lane >> 2);
        } else {
            int q = tile - 32, wq = q >> 3, j = q & 7;
            if (j < 6) {
                int n2 = (wq * 6 + j) * 8 + (lane >> 2);
                if (n2 < 256)      { W = Wf10; type = 0; ncol = n2; }
                else if (n2 < 512) { W = Wf20; type = 0; ncol = n2 - 256; }
                else               { W = Wh0;  type = 1; ncol = n2 - 512; }
            } else {
                W = Wm1; type = 2; ncol = (wq * 2 + (j - 6)) * 8 + (lane >> 2);
            }
        }
        auto srcrow = [&](int k) -> int {
            if (type == 0) return k < 256 ? k : ((k >= 258 && k < 262) ? k - 2 : -1);
            if (type == 1) return k < 256 ? k : (k < 258 ? k + 4 : (k < 262 ? k - 2 : -1));
            return k < 262 ? k : -1;
        };
        int s0 = srcrow(kk), s1 = srcrow(kk + 1);
        float v0 = (s0 >= 0) ? W[(size_t)s0 * 256 + ncol] : 0.f;
        float v1 = (s1 >= 0) ? W[(size_t)s1 * 256 + ncol] : 0.f;
        __nv_bfloat162 p;
        p.x = __float2bfloat16(v0);
        p.y = __float2bfloat16(v1);
        reinterpret_cast<unsigned*>(g_Wpk)[idx] = *reinterpret_cast<unsigned*>(&p);
    } else if (idx < total_u32 + 768) {
        int j = idx - total_u32;
        float4 v = make_float4(0.f, 0.f, 0.f, 0.f);
        if (j < 256)      { v.x = Wf11[j * 2];        v.y = Wf11[j * 2 + 1]; }
        else if (j < 512) { int q = j - 256;
                            v.x = Wf21[q * 4]; v.y = Wf21[q * 4 + 1];
                            v.z = Wf21[q * 4 + 2]; v.w = Wf21[q * 4 + 3]; }
        else              { int q = j - 512;
                            v.x = Wh1[q * 2];  v.y = Wh1[q * 2 + 1]; }
        g_smallW4[j] = v;
    }
}

// ---------------------------------------------------------------------------
__device__ __forceinline__ void mma16816(float* d, const unsigned* a, uint2 b) {
    asm volatile(
        "mma.sync.aligned.m16n8k16.row.col.f32.bf16.bf16.f32 "
        "{%0,%1,%2,%3}, {%4,%5,%6,%7}, {%8,%9}, {%0,%1,%2,%3};\n"
        : "+f"(d[0]), "+f"(d[1]), "+f"(d[2]), "+f"(d[3])
        : "r"(a[0]), "r"(a[1]), "r"(a[2]), "r"(a[3]), "r"(b.x), "r"(b.y));
}
__device__ __forceinline__ void ldmA(unsigned* a, unsigned addr) {
    asm volatile(
        "ldmatrix.sync.aligned.m8n8.x4.shared.b16 {%0,%1,%2,%3}, [%4];\n"
        : "=r"(a[0]), "=r"(a[1]), "=r"(a[2]), "=r"(a[3]) : "r"(addr));
}
__device__ __forceinline__ float tanha(float x) {
    float y; asm("tanh.approx.f32 %0, %1;" : "=f"(y) : "f"(x)); return y;
}

// M=16 GEMM over NT contiguous tiles (tile i at wbase + i*KSTEPS*32).
// Last NG3 tiles skip the final kstep. Register ring prefetch depth DEPTH.
template <int NT, int NG3>
__device__ __forceinline__ void run_gemm(const uint2* __restrict__ wbase,
                                         unsigned abase, float (&D)[NT][4]) {
    unsigned a[2][4];
    uint2 b[NT][DEPTH];
#pragma unroll
    for (int d = 0; d < DEPTH; d++)
#pragma unroll
        for (int i = 0; i < NT; i++)
            b[i][d] = wbase[(i * KSTEPS + d) * 32];
    ldmA(a[0], abase);
    int cur = 0;
#pragma unroll 1
    for (int ks = 0; ks < KSTEPS; ks++) {
        int ksn = (ks + 1 < KSTEPS) ? ks + 1 : ks;
        ldmA(a[(ks + 1) & 1], abase + (unsigned)ksn * 32u);
        bool last = (ks == KSTEPS - 1);
#pragma unroll
        for (int i = 0; i < NT; i++)
            if (i < NT - NG3 || !last)
                mma16816(D[i], a[ks & 1], b[i][cur]);
        if (ks + DEPTH < KSTEPS) {
#pragma unroll
            for (int i = 0; i < NT; i++)
                b[i][cur] = wbase[(i * KSTEPS + ks + DEPTH) * 32];
        }
        cur = (cur + 1 == DEPTH) ? 0 : cur + 1;
    }
}

__device__ __forceinline__ void write_act_tanh(int ntile, int cbase, int row0,
        const float (&D)[4], const float* __restrict__ bias,
        __nv_bfloat16 (*actp)[ACT_STRIDE]) {
    int col = ntile * 8 + cbase;
    float bv0 = bias[col], bv1 = bias[col + 1];
    __nv_bfloat162 h0, h1;
    h0.x = __float2bfloat16(tanha(D[0] + bv0));
    h0.y = __float2bfloat16(tanha(D[1] + bv1));
    h1.x = __float2bfloat16(tanha(D[2] + bv0));
    h1.y = __float2bfloat16(tanha(D[3] + bv1));
    *reinterpret_cast<__nv_bfloat162*>(&actp[row0][col]) = h0;
    *reinterpret_cast<__nv_bfloat162*>(&actp[row0 + 8][col]) = h1;
}

__device__ __forceinline__ void g2_epilogue(int tg, int cbase,
        const float (&D)[4], const float* __restrict__ bias2s,
        float (&o)[2][8]) {
    int col = tg * 8 + cbase;
    int seg = tg >> 5;  // 0: Wf11 (d), 1: Wf21 (pv), 2: Wh1 (hv)
    float bb0 = bias2s[col], bb1 = bias2s[col + 1];
    float4 w0 = g_smallW4[col];
    float4 w1 = g_smallW4[col + 1];
    int ob = (seg == 0) ? 0 : ((seg == 1) ? 2 : 6);
    float h0 = tanha(D[0] + bb0);
    float h1 = tanha(D[1] + bb1);
    float h2 = tanha(D[2] + bb0);
    float h3 = tanha(D[3] + bb1);
    o[0][ob + 0] += h0 * w0.x + h1 * w1.x;
    o[0][ob + 1] += h0 * w0.y + h1 * w1.y;
    o[1][ob + 0] += h2 * w0.x + h3 * w1.x;
    o[1][ob + 1] += h2 * w0.y + h3 * w1.y;
    if (seg == 1) {
        o[0][ob + 2] += h0 * w0.z + h1 * w1.z;
        o[0][ob + 3] += h0 * w0.w + h1 * w1.w;
        o[1][ob + 2] += h2 * w0.z + h3 * w1.z;
        o[1][ob + 3] += h2 * w0.w + h3 * w1.w;
    }
}

// ---------------------------------------------------------------------------
// Main persistent kernel: 128 CTAs x 512 threads, 16 batch rows per CTA.
// ---------------------------------------------------------------------------
__global__ void __launch_bounds__(NTHREADS, 1) egbrnn_main(
    const float* __restrict__ x, const float* __restrict__ target,
    const float* __restrict__ c0,
    const float* __restrict__ bm0, const float* __restrict__ bm1,
    const float* __restrict__ bf10, const float* __restrict__ bf11,
    const float* __restrict__ bf20, const float* __restrict__ bf21,
    const float* __restrict__ bh0, const float* __restrict__ bh1,
    float* __restrict__ out)
{
    __shared__ __align__(16) __nv_bfloat16 act[MCTA][ACT_STRIDE];
    __shared__ float sS[MCTA][4];
    __shared__ float Pm[MCTA][16];
    __shared__ float measS[MCTA][2];
    __shared__ float part[NWARPS][MCTA][9];
    __shared__ float bm0s[256], bm1s[256], bias2s[768], biasSs[8];

    const int tid = threadIdx.x;
    const int w = tid >> 5, lane = tid & 31;
    const int b0 = blockIdx.x * MCTA;
    const int row0 = lane >> 2;
    const int cbase = (lane & 3) * 2;

    // ---- one-time shared init ----
    if (tid < 256) { bm0s[tid] = bm0[tid]; bm1s[tid] = bm1[tid]; }
    for (int i = tid; i < 768; i += NTHREADS)
        bias2s[i] = (i < 256) ? bf10[i] : (i < 512 ? bf20[i - 256] : bh0[i - 512]);
    if (tid < 8)
        biasSs[tid] = (tid < 2) ? bf11[tid] : (tid < 6 ? bf21[tid - 2] : bh1[tid - 6]);
    for (int i = tid; i < MCTA * 24; i += NTHREADS) {   // zero cols 256..279
        int r = i / 24, c = 256 + i % 24;
        act[r][c] = __float2bfloat16(0.f);
    }
    for (int i = tid; i < MCTA * 256; i += NTHREADS) {  // c = c0
        int r = i >> 8, j = i & 255;
        act[r][j] = __float2bfloat16(c0[(size_t)(b0 + r) * 256 + j]);
    }
    __syncthreads();
    if (tid < MCTA) {
        int r = tid;
        float4 tg = *reinterpret_cast<const float4*>(
            &target[((size_t)(b0 + r) * T_STEPS) * 4]);
        sS[r][0] = tg.x; sS[r][1] = tg.y; sS[r][2] = tg.z; sS[r][3] = tg.w;
#pragma unroll
        for (int i = 0; i < 16; i++) Pm[r][i] = (i % 5 == 0) ? 1.f : 0.f;
        __nv_bfloat162 a01, a23;
        a01.x = __float2bfloat16(tg.x * (1.f / 60.f));
        a01.y = __float2bfloat16(tg.y * (1.f / 60.f));
        a23.x = __float2bfloat16(tg.z * (1.f / 60.f));
        a23.y = __float2bfloat16(tg.w * (1.f / 60.f));
        *reinterpret_cast<__nv_bfloat162*>(&act[r][258]) = a01;  // s/60
        *reinterpret_cast<__nv_bfloat162*>(&act[r][260]) = a23;
    }
    __syncthreads();

    const unsigned ab0 =
        (unsigned)__cvta_generic_to_shared(&act[lane & 15][(lane >> 4) * 8]);
    const uint2* wG1 = g_Wpk + (2 * w) * KSTEPS * 32 + lane;
    const uint2* wP3 = g_Wpk + (32 + w * 8) * KSTEPS * 32 + lane;

    for (int t = 0; t < T_STEPS; t++) {
        // ---- P1: GEMM1 (cu preactivation) ----
        float D1[2][4];
#pragma unroll
        for (int i = 0; i < 2; i++)
            D1[i][0] = D1[i][1] = D1[i][2] = D1[i][3] = 0.f;
        run_gemm<2, 0>(wG1, ab0, D1);
        __syncthreads();

        // ---- P2: write cu over c; load meas; write m2 ----
        write_act_tanh(2 * w,     cbase, row0, D1[0], bm0s, act);
        write_act_tanh(2 * w + 1, cbase, row0, D1[1], bm0s, act);
        if (tid < MCTA) {
            int r = tid;
            float2 m = *reinterpret_cast<const float2*>(
                &x[(((size_t)(b0 + r)) * T_STEPS + t) * 2]);
            measS[r][0] = m.x; measS[r][1] = m.y;
            __nv_bfloat162 mm;
            mm.x = __float2bfloat16(m.x * (1.f / 60.f));
            mm.y = __float2bfloat16(m.y * (1.f / 60.f));
            *reinterpret_cast<__nv_bfloat162*>(&act[r][256]) = mm;
        }
        __syncthreads();

        // ---- P3: fused GEMM2 (6 tiles) + GEMM3 ksteps 0..15 (2 tiles) ----
        uint2 b3last0 = wP3[(6 * KSTEPS + 16) * 32];
        uint2 b3last1 = wP3[(7 * KSTEPS + 16) * 32];
        float D2[8][4];
#pragma unroll
        for (int i = 0; i < 8; i++)
            D2[i][0] = D2[i][1] = D2[i][2] = D2[i][3] = 0.f;
        run_gemm<8, 2>(wP3, ab0, D2);
        float o[2][8];
#pragma unroll
        for (int s = 0; s < 2; s++)
#pragma unroll
            for (int k = 0; k < 8; k++) o[s][k] = 0.f;
#pragma unroll
        for (int j = 0; j < 6; j++)
            g2_epilogue(6 * w + j, cbase, D2[j], bias2s, o);
#pragma unroll
        for (int s = 0; s < 2; s++)
#pragma unroll
            for (int k = 0; k < 8; k++) {
                o[s][k] += __shfl_xor_sync(0xffffffffu, o[s][k], 1);
                o[s][k] += __shfl_xor_sync(0xffffffffu, o[s][k], 2);
            }
        if ((lane & 3) == 0) {
#pragma unroll
            for (int k = 0; k < 8; k++) {
                part[w][row0][k]     = o[0][k];
                part[w][row0 + 8][k] = o[1][k];
            }
        }
        __syncthreads();

        // ---- P4: per-row Kalman update (fp32) ----
        if (tid < MCTA) {
            const int r = tid;
            float sm[8];
#pragma unroll
            for (int k = 0; k < 8; k++) {
                float a = biasSs[k];
#pragma unroll
                for (int ww = 0; ww < NWARPS; ww++) a += part[ww][r][k];
                sm[k] = a;
            }
            const float d0 = sm[0], d1 = sm[1];
            const float pv[4] = {sm[2], sm[3], sm[4], sm[5]};
            const float hv0 = sm[6], hv1 = sm[7];
            float s0 = sS[r][0], s1 = sS[r][1], s2 = sS[r][2], s3 = sS[r][3];
            float sp[4];
            sp[0] = s0 + s2 + 0.5f * d0;
            sp[1] = s1 + s3 + 0.5f * d1;
            sp[2] = s2 + d0;
            sp[3] = s3 + d1;
            float P[4][4];
#pragma unroll
            for (int i = 0; i < 4; i++)
#pragma unroll
                for (int j = 0; j < 4; j++) P[i][j] = Pm[r][i * 4 + j];
            float FP[4][4], Pp[4][4];
#pragma unroll
            for (int j = 0; j < 4; j++) {
                FP[0][j] = P[0][j] + P[2][j];
                FP[1][j] = P[1][j] + P[3][j];
                FP[2][j] = P[2][j];
                FP[3][j] = P[3][j];
            }
#pragma unroll
            for (int i = 0; i < 4; i++) {
                Pp[i][0] = FP[i][0] + FP[i][2];
                Pp[i][1] = FP[i][1] + FP[i][3];
                Pp[i][2] = FP[i][2];
                Pp[i][3] = FP[i][3];
            }
#pragma unroll
            for (int i = 0; i < 4; i++)
#pragma unroll
                for (int j = 0; j < 4; j++) Pp[i][j] += pv[i] * pv[j];
#pragma unroll
            for (int i = 0; i < 4; i++) Pp[i][i] += 0.01f;
            float m0 = measS[r][0], m1 = measS[r][1];
            float in0 = m0 - sp[0], in1 = m1 - sp[1];
            float S00 = Pp[0][0] + hv0 * hv0 + 1.f;
            float S01 = Pp[0][1] + hv0 * hv1;
            float S10 = Pp[1][0] + hv1 * hv0;
            float S11 = Pp[1][1] + hv1 * hv1 + 1.f;
            float inv = 1.0f / (S00 * S11 - S01 * S10);
            float K[4][2], KS[4][2], su[4];
#pragma unroll
            for (int i = 0; i < 4; i++) {
                K[i][0] = (Pp[i][0] * S11 - Pp[i][1] * S10) * inv;
                K[i][1] = (Pp[i][1] * S00 - Pp[i][0] * S01) * inv;
                su[i] = sp[i] + K[i][0] * in0 + K[i][1] * in1;
                KS[i][0] = K[i][0] * S00 + K[i][1] * S10;
                KS[i][1] = K[i][0] * S01 + K[i][1] * S11;
            }
#pragma unroll
            for (int i = 0; i < 4; i++)
#pragma unroll
                for (int j = 0; j < 4; j++)
                    Pm[r][i * 4 + j] =
                        Pp[i][j] - KS[i][0] * K[j][0] - KS[i][1] * K[j][1];
            sS[r][0] = su[0]; sS[r][1] = su[1];
            sS[r][2] = su[2]; sS[r][3] = su[3];
            float4 ov = make_float4(su[0], su[1], su[2], su[3]);
            *reinterpret_cast<float4*>(
                &out[(((size_t)(b0 + r)) * T_STEPS + t) * 4]) = ov;
            __nv_bfloat162 q0, q1;
            q0.x = __float2bfloat16(su[0] * (1.f / 60.f));
            q0.y = __float2bfloat16(su[1] * (1.f / 60.f));
            q1.x = __float2bfloat16(su[2] * (1.f / 60.f));
            q1.y = __float2bfloat16(su[3] * (1.f / 60.f));
            *reinterpret_cast<__nv_bfloat162*>(&act[r][258]) = q0;  // su/60 == next sn
            *reinterpret_cast<__nv_bfloat162*>(&act[r][260]) = q1;
        }
        __syncthreads();

        // ---- P5: GEMM3 final kstep (reads tail cols 256..271) + c_new ----
        {
            unsigned a0[4];
            ldmA(a0, ab0 + 16u * 32u);
            mma16816(D2[6], a0, b3last0);
            mma16816(D2[7], a0, b3last1);
        }
        write_act_tanh(2 * w,     cbase, row0, D2[6], bm1s, act);
        write_act_tanh(2 * w + 1, cbase, row0, D2[7], bm1s, act);
        __syncthreads();
    }
}

// ---------------------------------------------------------------------------
extern "C" void kernel_launch(void* const* d_in, const int* in_sizes, int n_in,
                              void* d_out, int out_size)
{
    const float* x    = (const float*)d_in[0];
    const float* targ = (const float*)d_in[1];
    const float* c0   = (const float*)d_in[2];
    const float* Wm0  = (const float*)d_in[3];
    const float* bm0  = (const float*)d_in[4];
    const float* Wm1  = (const float*)d_in[5];
    const float* bm1  = (const float*)d_in[6];
    const float* Wf10 = (const float*)d_in[7];
    const float* bf10 = (const float*)d_in[8];
    const float* Wf11 = (const float*)d_in[9];
    const float* bf11 = (const float*)d_in[10];
    const float* Wf20 = (const float*)d_in[11];
    const float* bf20 = (const float*)d_in[12];
    const float* Wf21 = (const float*)d_in[13];
    const float* bf21 = (const float*)d_in[14];
    const float* Wh0  = (const float*)d_in[15];
    const float* bh0  = (const float*)d_in[16];
    const float* Wh1  = (const float*)d_in[17];
    const float* bh1  = (const float*)d_in[18];
    float* out = (float*)d_out;

    const int tot = 160 * 17 * 32 * 2 + 768;
    prepack_kernel<<<(tot + 255) / 256, 256>>>(Wm0, Wf10, Wf20, Wh0, Wm1,
                                               Wf11, Wf21, Wh1);
    egbrnn_main<<<NCTAS, NTHREADS>>>(x, targ, c0, bm0, bm1, bf10, bf11,
                                     bf20, bf21, bh0, bh1, out);
}

// round 5
// speedup vs baseline: 2.9210x; 2.7254x over previous
#include <cuda_runtime.h>
#include <cuda_bf16.h>

#define MCTA 16
#define NCTAS 128
#define NTHREADS 256
#define NWARPS 8
#define T_STEPS 128
#define KSTEPS 17
#define ACT_STRIDE 280   // bf16 elems per row

// Packed weights, fragment order. Tile map (8 warps):
//   T in [0,32):    GEMM1 (Wm0), warp w owns T = 4w..4w+3  (N cols [32w,32w+32))
//   T in [32,160):  per-warp P3 block: q=T-32, w=q/16, j=q%16
//                   j<12  -> GEMM2 tile tg=(12w+j)  (Wf10|Wf20|Wh0, n2=8*tg)
//                   j>=12 -> GEMM3 (Wm1) n-tile 4w+(j-12)
__device__ uint2 g_Wpk[160 * 17 * 32];
__device__ float4 g_smallW4[768];

// ---------------------------------------------------------------------------
// Activation column layout (padded K = 272):
//   0..255: c / cu / c_new    256..257: meas/60    258..261: s/60   262..271: 0
// Row remap: type0 (Wm0,Wf10,Wf20;fin260): k<256->k, 258..261->k-2
//            type1 (Wh0;fin262): k<256->k, 256,257->k+4, 258..261->k-2
//            type2 (Wm1;fin262): identity
// ---------------------------------------------------------------------------
__global__ void prepack_kernel(
    const float* __restrict__ Wm0, const float* __restrict__ Wf10,
    const float* __restrict__ Wf20, const float* __restrict__ Wh0,
    const float* __restrict__ Wm1, const float* __restrict__ Wf11,
    const float* __restrict__ Wf21, const float* __restrict__ Wh1)
{
    const int total_u32 = 160 * 17 * 32 * 2;
    int idx = blockIdx.x * blockDim.x + threadIdx.x;
    if (idx < total_u32) {
        int r    = idx & 1;
        int lane = (idx >> 1) & 31;
        int tk   = idx >> 6;          // tile*17 + ks
        int ks   = tk % 17;
        int tile = tk / 17;
        int kk = ks * 16 + (lane & 3) * 2 + r * 8;
        const float* W; int type; int ncol;
        if (tile < 32) {
            W = Wm0; type = 0; ncol = tile * 8 + (lane >> 2);
        } else {
            int q = tile - 32, wq = q >> 4, j = q & 15;
            if (j < 12) {
                int n2 = (wq * 12 + j) * 8 + (lane >> 2);
                if (n2 < 256)      { W = Wf10; type = 0; ncol = n2; }
                else if (n2 < 512) { W = Wf20; type = 0; ncol = n2 - 256; }
                else               { W = Wh0;  type = 1; ncol = n2 - 512; }
            } else {
                W = Wm1; type = 2; ncol = (wq * 4 + (j - 12)) * 8 + (lane >> 2);
            }
        }
        auto srcrow = [&](int k) -> int {
            if (type == 0) return k < 256 ? k : ((k >= 258 && k < 262) ? k - 2 : -1);
            if (type == 1) return k < 256 ? k : (k < 258 ? k + 4 : (k < 262 ? k - 2 : -1));
            return k < 262 ? k : -1;
        };
        int s0 = srcrow(kk), s1 = srcrow(kk + 1);
        float v0 = (s0 >= 0) ? W[(size_t)s0 * 256 + ncol] : 0.f;
        float v1 = (s1 >= 0) ? W[(size_t)s1 * 256 + ncol] : 0.f;
        __nv_bfloat162 p;
        p.x = __float2bfloat16(v0);
        p.y = __float2bfloat16(v1);
        reinterpret_cast<unsigned*>(g_Wpk)[idx] = *reinterpret_cast<unsigned*>(&p);
    } else if (idx < total_u32 + 768) {
        int j = idx - total_u32;
        float4 v = make_float4(0.f, 0.f, 0.f, 0.f);
        if (j < 256)      { v.x = Wf11[j * 2];        v.y = Wf11[j * 2 + 1]; }
        else if (j < 512) { int q = j - 256;
                            v.x = Wf21[q * 4]; v.y = Wf21[q * 4 + 1];
                            v.z = Wf21[q * 4 + 2]; v.w = Wf21[q * 4 + 3]; }
        else              { int q = j - 512;
                            v.x = Wh1[q * 2];  v.y = Wh1[q * 2 + 1]; }
        g_smallW4[j] = v;
    }
}

// ---------------------------------------------------------------------------
__device__ __forceinline__ void mma16816(float* d, const unsigned* a, uint2 b) {
    asm volatile(
        "mma.sync.aligned.m16n8k16.row.col.f32.bf16.bf16.f32 "
        "{%0,%1,%2,%3}, {%4,%5,%6,%7}, {%8,%9}, {%0,%1,%2,%3};\n"
        : "+f"(d[0]), "+f"(d[1]), "+f"(d[2]), "+f"(d[3])
        : "r"(a[0]), "r"(a[1]), "r"(a[2]), "r"(a[3]), "r"(b.x), "r"(b.y));
}
__device__ __forceinline__ void ldmA(unsigned* a, unsigned addr) {
    asm volatile(
        "ldmatrix.sync.aligned.m8n8.x4.shared.b16 {%0,%1,%2,%3}, [%4];\n"
        : "=r"(a[0]), "=r"(a[1]), "=r"(a[2]), "=r"(a[3]) : "r"(addr));
}
__device__ __forceinline__ float tanha(float x) {
    float y; asm("tanh.approx.f32 %0, %1;" : "=f"(y) : "f"(x)); return y;
}

// M=16 GEMM over NT contiguous tiles (tile i at wb + i*KSTEPS*32).
// FULLY UNROLLED k-loop: all register-array indices are compile-time.
// 2-slot B buffer, prefetch distance 2; ping-pong A ldmatrix distance 1.
// Last NG3 tiles skip the final kstep.
template <int NT, int NG3>
__device__ __forceinline__ void run_gemm(const uint2* __restrict__ wb,
                                         unsigned abase, float (&D)[NT][4]) {
    unsigned a[2][4];
    uint2 b[NT][2];
#pragma unroll
    for (int i = 0; i < NT; i++) {
        b[i][0] = wb[(i * KSTEPS + 0) * 32];
        b[i][1] = wb[(i * KSTEPS + 1) * 32];
    }
    ldmA(a[0], abase);
#pragma unroll
    for (int ks = 0; ks < KSTEPS; ks++) {
        if (ks + 1 < KSTEPS)
            ldmA(a[(ks + 1) & 1], abase + (unsigned)(ks + 1) * 32u);
#pragma unroll
        for (int i = 0; i < NT; i++) {
            if (i < NT - NG3 || ks < KSTEPS - 1)
                mma16816(D[i], a[ks & 1], b[i][ks & 1]);
            if (ks + 2 < KSTEPS)
                b[i][ks & 1] = wb[(i * KSTEPS + ks + 2) * 32];
        }
    }
}

__device__ __forceinline__ void write_act_tanh(int ntile, int cbase, int row0,
        const float (&D)[4], const float* __restrict__ bias,
        __nv_bfloat16 (*actp)[ACT_STRIDE]) {
    int col = ntile * 8 + cbase;
    float bv0 = bias[col], bv1 = bias[col + 1];
    __nv_bfloat162 h0, h1;
    h0.x = __float2bfloat16(tanha(D[0] + bv0));
    h0.y = __float2bfloat16(tanha(D[1] + bv1));
    h1.x = __float2bfloat16(tanha(D[2] + bv0));
    h1.y = __float2bfloat16(tanha(D[3] + bv1));
    *reinterpret_cast<__nv_bfloat162*>(&actp[row0][col]) = h0;
    *reinterpret_cast<__nv_bfloat162*>(&actp[row0 + 8][col]) = h1;
}

__device__ __forceinline__ void g2_epilogue(int tg, int cbase,
        const float (&D)[4], const float* __restrict__ bias2s,
        const float4* __restrict__ smallWs, float (&o)[2][8]) {
    int col = tg * 8 + cbase;
    int seg = tg >> 5;  // 0: Wf11 (d), 1: Wf21 (pv), 2: Wh1 (hv)
    float bb0 = bias2s[col], bb1 = bias2s[col + 1];
    float4 w0 = smallWs[col];
    float4 w1 = smallWs[col + 1];
    int ob = (seg == 0) ? 0 : ((seg == 1) ? 2 : 6);
    float h0 = tanha(D[0] + bb0);
    float h1 = tanha(D[1] + bb1);
    float h2 = tanha(D[2] + bb0);
    float h3 = tanha(D[3] + bb1);
    o[0][ob + 0] += h0 * w0.x + h1 * w1.x;
    o[0][ob + 1] += h0 * w0.y + h1 * w1.y;
    o[1][ob + 0] += h2 * w0.x + h3 * w1.x;
    o[1][ob + 1] += h2 * w0.y + h3 * w1.y;
    if (seg == 1) {
        o[0][ob + 2] += h0 * w0.z + h1 * w1.z;
        o[0][ob + 3] += h0 * w0.w + h1 * w1.w;
        o[1][ob + 2] += h2 * w0.z + h3 * w1.z;
        o[1][ob + 3] += h2 * w0.w + h3 * w1.w;
    }
}

// ---------------------------------------------------------------------------
// Main persistent kernel: 128 CTAs x 256 threads, 16 batch rows per CTA.
// ---------------------------------------------------------------------------
__global__ void __launch_bounds__(NTHREADS, 1) egbrnn_main(
    const float* __restrict__ x, const float* __restrict__ target,
    const float* __restrict__ c0,
    const float* __restrict__ bm0, const float* __restrict__ bm1,
    const float* __restrict__ bf10, const float* __restrict__ bf11,
    const float* __restrict__ bf20, const float* __restrict__ bf21,
    const float* __restrict__ bh0, const float* __restrict__ bh1,
    float* __restrict__ out)
{
    __shared__ __align__(16) __nv_bfloat16 act[MCTA][ACT_STRIDE];
    __shared__ float sS[MCTA][4];
    __shared__ float Pm[MCTA][16];
    __shared__ float measS[MCTA][2];
    __shared__ float part[NWARPS][MCTA][9];
    __shared__ float bm0s[256], bm1s[256], bias2s[768], biasSs[8];
    __shared__ __align__(16) float4 smallWs[768];

    const int tid = threadIdx.x;
    const int w = tid >> 5, lane = tid & 31;
    const int b0 = blockIdx.x * MCTA;
    const int row0 = lane >> 2;
    const int cbase = (lane & 3) * 2;

    // ---- one-time shared init ----
    bm0s[tid] = bm0[tid];
    bm1s[tid] = bm1[tid];
    for (int i = tid; i < 768; i += NTHREADS) {
        bias2s[i] = (i < 256) ? bf10[i] : (i < 512 ? bf20[i - 256] : bh0[i - 512]);
        smallWs[i] = g_smallW4[i];
    }
    if (tid < 8)
        biasSs[tid] = (tid < 2) ? bf11[tid] : (tid < 6 ? bf21[tid - 2] : bh1[tid - 6]);
    for (int i = tid; i < MCTA * 24; i += NTHREADS) {   // zero cols 256..279
        int r = i / 24, c = 256 + i % 24;
        act[r][c] = __float2bfloat16(0.f);
    }
    for (int i = tid; i < MCTA * 256; i += NTHREADS) {  // c = c0
        int r = i >> 8, j = i & 255;
        act[r][j] = __float2bfloat16(c0[(size_t)(b0 + r) * 256 + j]);
    }
    __syncthreads();
    if (tid < MCTA) {
        int r = tid;
        float4 tg = *reinterpret_cast<const float4*>(
            &target[((size_t)(b0 + r) * T_STEPS) * 4]);
        sS[r][0] = tg.x; sS[r][1] = tg.y; sS[r][2] = tg.z; sS[r][3] = tg.w;
#pragma unroll
        for (int i = 0; i < 16; i++) Pm[r][i] = (i % 5 == 0) ? 1.f : 0.f;
        __nv_bfloat162 a01, a23;
        a01.x = __float2bfloat16(tg.x * (1.f / 60.f));
        a01.y = __float2bfloat16(tg.y * (1.f / 60.f));
        a23.x = __float2bfloat16(tg.z * (1.f / 60.f));
        a23.y = __float2bfloat16(tg.w * (1.f / 60.f));
        *reinterpret_cast<__nv_bfloat162*>(&act[r][258]) = a01;  // s/60
        *reinterpret_cast<__nv_bfloat162*>(&act[r][260]) = a23;
    }
    __syncthreads();

    const unsigned ab0 =
        (unsigned)__cvta_generic_to_shared(&act[lane & 15][(lane >> 4) * 8]);
    const uint2* wG1 = g_Wpk + (4 * w) * KSTEPS * 32 + lane;
    const uint2* wP3 = g_Wpk + (32 + 16 * w) * KSTEPS * 32 + lane;

    for (int t = 0; t < T_STEPS; t++) {
        // ---- P1: GEMM1 (cu preactivation), 4 tiles/warp ----
        float D1[4][4];
#pragma unroll
        for (int i = 0; i < 4; i++)
            D1[i][0] = D1[i][1] = D1[i][2] = D1[i][3] = 0.f;
        run_gemm<4, 0>(wG1, ab0, D1);
        __syncthreads();

        // ---- P2: write cu over c; load meas; write m2 ----
#pragma unroll
        for (int tt = 0; tt < 4; tt++)
            write_act_tanh(4 * w + tt, cbase, row0, D1[tt], bm0s, act);
        if (tid < MCTA) {
            int r = tid;
            float2 m = *reinterpret_cast<const float2*>(
                &x[(((size_t)(b0 + r)) * T_STEPS + t) * 2]);
            measS[r][0] = m.x; measS[r][1] = m.y;
            __nv_bfloat162 mm;
            mm.x = __float2bfloat16(m.x * (1.f / 60.f));
            mm.y = __float2bfloat16(m.y * (1.f / 60.f));
            *reinterpret_cast<__nv_bfloat162*>(&act[r][256]) = mm;
        }
        __syncthreads();

        // ---- P3: fused GEMM2 (12 tiles) + GEMM3 ks 0..15 (4 tiles) ----
        uint2 b3l[4];
#pragma unroll
        for (int tt = 0; tt < 4; tt++)
            b3l[tt] = wP3[((12 + tt) * KSTEPS + 16) * 32];
        float D2[16][4];
#pragma unroll
        for (int i = 0; i < 16; i++)
            D2[i][0] = D2[i][1] = D2[i][2] = D2[i][3] = 0.f;
        run_gemm<16, 4>(wP3, ab0, D2);
        float o[2][8];
#pragma unroll
        for (int s = 0; s < 2; s++)
#pragma unroll
            for (int k = 0; k < 8; k++) o[s][k] = 0.f;
#pragma unroll
        for (int j = 0; j < 12; j++)
            g2_epilogue(12 * w + j, cbase, D2[j], bias2s, smallWs, o);
#pragma unroll
        for (int s = 0; s < 2; s++)
#pragma unroll
            for (int k = 0; k < 8; k++) {
                o[s][k] += __shfl_xor_sync(0xffffffffu, o[s][k], 1);
                o[s][k] += __shfl_xor_sync(0xffffffffu, o[s][k], 2);
            }
        if ((lane & 3) == 0) {
#pragma unroll
            for (int k = 0; k < 8; k++) {
                part[w][row0][k]     = o[0][k];
                part[w][row0 + 8][k] = o[1][k];
            }
        }
        __syncthreads();

        // ---- P4: per-row Kalman update (fp32) ----
        if (tid < MCTA) {
            const int r = tid;
            float sm[8];
#pragma unroll
            for (int k = 0; k < 8; k++) {
                float a = biasSs[k];
#pragma unroll
                for (int ww = 0; ww < NWARPS; ww++) a += part[ww][r][k];
                sm[k] = a;
            }
            const float d0 = sm[0], d1 = sm[1];
            const float pv[4] = {sm[2], sm[3], sm[4], sm[5]};
            const float hv0 = sm[6], hv1 = sm[7];
            float s0 = sS[r][0], s1 = sS[r][1], s2 = sS[r][2], s3 = sS[r][3];
            float sp[4];
            sp[0] = s0 + s2 + 0.5f * d0;
            sp[1] = s1 + s3 + 0.5f * d1;
            sp[2] = s2 + d0;
            sp[3] = s3 + d1;
            float P[4][4];
#pragma unroll
            for (int i = 0; i < 4; i++)
#pragma unroll
                for (int j = 0; j < 4; j++) P[i][j] = Pm[r][i * 4 + j];
            float FP[4][4], Pp[4][4];
#pragma unroll
            for (int j = 0; j < 4; j++) {
                FP[0][j] = P[0][j] + P[2][j];
                FP[1][j] = P[1][j] + P[3][j];
                FP[2][j] = P[2][j];
                FP[3][j] = P[3][j];
            }
#pragma unroll
            for (int i = 0; i < 4; i++) {
                Pp[i][0] = FP[i][0] + FP[i][2];
                Pp[i][1] = FP[i][1] + FP[i][3];
                Pp[i][2] = FP[i][2];
                Pp[i][3] = FP[i][3];
            }
#pragma unroll
            for (int i = 0; i < 4; i++)
#pragma unroll
                for (int j = 0; j < 4; j++) Pp[i][j] += pv[i] * pv[j];
#pragma unroll
            for (int i = 0; i < 4; i++) Pp[i][i] += 0.01f;
            float m0 = measS[r][0], m1 = measS[r][1];
            float in0 = m0 - sp[0], in1 = m1 - sp[1];
            float S00 = Pp[0][0] + hv0 * hv0 + 1.f;
            float S01 = Pp[0][1] + hv0 * hv1;
            float S10 = Pp[1][0] + hv1 * hv0;
            float S11 = Pp[1][1] + hv1 * hv1 + 1.f;
            float inv = 1.0f / (S00 * S11 - S01 * S10);
            float K[4][2], KS[4][2], su[4];
#pragma unroll
            for (int i = 0; i < 4; i++) {
                K[i][0] = (Pp[i][0] * S11 - Pp[i][1] * S10) * inv;
                K[i][1] = (Pp[i][1] * S00 - Pp[i][0] * S01) * inv;
                su[i] = sp[i] + K[i][0] * in0 + K[i][1] * in1;
                KS[i][0] = K[i][0] * S00 + K[i][1] * S10;
                KS[i][1] = K[i][0] * S01 + K[i][1] * S11;
            }
#pragma unroll
            for (int i = 0; i < 4; i++)
#pragma unroll
                for (int j = 0; j < 4; j++)
                    Pm[r][i * 4 + j] =
                        Pp[i][j] - KS[i][0] * K[j][0] - KS[i][1] * K[j][1];
            sS[r][0] = su[0]; sS[r][1] = su[1];
            sS[r][2] = su[2]; sS[r][3] = su[3];
            float4 ov = make_float4(su[0], su[1], su[2], su[3]);
            *reinterpret_cast<float4*>(
                &out[(((size_t)(b0 + r)) * T_STEPS + t) * 4]) = ov;
            __nv_bfloat162 q0, q1;
            q0.x = __float2bfloat16(su[0] * (1.f / 60.f));
            q0.y = __float2bfloat16(su[1] * (1.f / 60.f));
            q1.x = __float2bfloat16(su[2] * (1.f / 60.f));
            q1.y = __float2bfloat16(su[3] * (1.f / 60.f));
            *reinterpret_cast<__nv_bfloat162*>(&act[r][258]) = q0;  // su/60 == next sn
            *reinterpret_cast<__nv_bfloat162*>(&act[r][260]) = q1;
        }
        __syncthreads();

        // ---- P5: GEMM3 final kstep (reads tail cols 256..271) + c_new.
        //      Reads only cols 256..271, writes only cols 0..255: disjoint. ----
        {
            unsigned a0[4];
            ldmA(a0, ab0 + 16u * 32u);
            mma16816(D2[12], a0, b3l[0]);
            mma16816(D2[13], a0, b3l[1]);
            mma16816(D2[14], a0, b3l[2]);
            mma16816(D2[15], a0, b3l[3]);
        }
#pragma unroll
        for (int tt = 0; tt < 4; tt++)
            write_act_tanh(4 * w + tt, cbase, row0, D2[12 + tt], bm1s, act);
        __syncthreads();
    }
}

// ---------------------------------------------------------------------------
extern "C" void kernel_launch(void* const* d_in, const int* in_sizes, int n_in,
                              void* d_out, int out_size)
{
    const float* x    = (const float*)d_in[0];
    const float* targ = (const float*)d_in[1];
    const float* c0   = (const float*)d_in[2];
    const float* Wm0  = (const float*)d_in[3];
    const float* bm0  = (const float*)d_in[4];
    const float* Wm1  = (const float*)d_in[5];
    const float* bm1  = (const float*)d_in[6];
    const float* Wf10 = (const float*)d_in[7];
    const float* bf10 = (const float*)d_in[8];
    const float* Wf11 = (const float*)d_in[9];
    const float* bf11 = (const float*)d_in[10];
    const float* Wf20 = (const float*)d_in[11];
    const float* bf20 = (const float*)d_in[12];
    const float* Wf21 = (const float*)d_in[13];
    const float* bf21 = (const float*)d_in[14];
    const float* Wh0  = (const float*)d_in[15];
    const float* bh0  = (const float*)d_in[16];
    const float* Wh1  = (const float*)d_in[17];
    const float* bh1  = (const float*)d_in[18];
    float* out = (float*)d_out;

    const int tot = 160 * 17 * 32 * 2 + 768;
    prepack_kernel<<<(tot + 255) / 256, 256>>>(Wm0, Wf10, Wf20, Wh0, Wm1,
                                               Wf11, Wf21, Wh1);
    egbrnn_main<<<NCTAS, NTHREADS>>>(x, targ, c0, bm0, bm1, bf10, bf11,
                                     bf20, bf21, bh0, bh1, out);
}

// round 6
// speedup vs baseline: 3.3351x; 1.1418x over previous
#include <cuda_runtime.h>
#include <cuda_bf16.h>

#define MCTA 16
#define NCTAS 128
#define NTHREADS 512
#define NWARPS 16
#define T_STEPS 128
#define KSTEPS 17
#define ACT_STRIDE 280   // bf16 elems per row

// Packed weights, fragment order. Tile map (16 warps):
//   T in [0,32):    GEMM1 (Wm0), warp w owns T = 2w, 2w+1 (N cols [16w,16w+16))
//   T in [32,160):  per-warp P3 block: q=T-32, w=q/8, j=q%8
//                   j<6  -> GEMM2 tile tg=(6w+j)  (Wf10|Wf20|Wh0, n2=8*tg)
//                   j>=6 -> GEMM3 (Wm1) n-tile 2w+(j-6)
__device__ uint2 g_Wpk[160 * 17 * 32];
__device__ float4 g_smallW4[768];

// ---------------------------------------------------------------------------
// Activation column layout (padded K = 272):
//   0..255: c / cu / c_new    256..257: meas/60    258..261: s/60   262..271: 0
// Row remap: type0 (Wm0,Wf10,Wf20;fin260): k<256->k, 258..261->k-2
//            type1 (Wh0;fin262): k<256->k, 256,257->k+4, 258..261->k-2
//            type2 (Wm1;fin262): identity
// ---------------------------------------------------------------------------
__global__ void prepack_kernel(
    const float* __restrict__ Wm0, const float* __restrict__ Wf10,
    const float* __restrict__ Wf20, const float* __restrict__ Wh0,
    const float* __restrict__ Wm1, const float* __restrict__ Wf11,
    const float* __restrict__ Wf21, const float* __restrict__ Wh1)
{
    const int total_u32 = 160 * 17 * 32 * 2;
    int idx = blockIdx.x * blockDim.x + threadIdx.x;
    if (idx < total_u32) {
        int r    = idx & 1;
        int lane = (idx >> 1) & 31;
        int tk   = idx >> 6;          // tile*17 + ks
        int ks   = tk % 17;
        int tile = tk / 17;
        int kk = ks * 16 + (lane & 3) * 2 + r * 8;
        const float* W; int type; int ncol;
        if (tile < 32) {
            W = Wm0; type = 0; ncol = tile * 8 + (lane >> 2);
        } else {
            int q = tile - 32, wq = q >> 3, j = q & 7;
            if (j < 6) {
                int n2 = (wq * 6 + j) * 8 + (lane >> 2);
                if (n2 < 256)      { W = Wf10; type = 0; ncol = n2; }
                else if (n2 < 512) { W = Wf20; type = 0; ncol = n2 - 256; }
                else               { W = Wh0;  type = 1; ncol = n2 - 512; }
            } else {
                W = Wm1; type = 2; ncol = (wq * 2 + (j - 6)) * 8 + (lane >> 2);
            }
        }
        auto srcrow = [&](int k) -> int {
            if (type == 0) return k < 256 ? k : ((k >= 258 && k < 262) ? k - 2 : -1);
            if (type == 1) return k < 256 ? k : (k < 258 ? k + 4 : (k < 262 ? k - 2 : -1));
            return k < 262 ? k : -1;
        };
        int s0 = srcrow(kk), s1 = srcrow(kk + 1);
        float v0 = (s0 >= 0) ? W[(size_t)s0 * 256 + ncol] : 0.f;
        float v1 = (s1 >= 0) ? W[(size_t)s1 * 256 + ncol] : 0.f;
        __nv_bfloat162 p;
        p.x = __float2bfloat16(v0);
        p.y = __float2bfloat16(v1);
        reinterpret_cast<unsigned*>(g_Wpk)[idx] = *reinterpret_cast<unsigned*>(&p);
    } else if (idx < total_u32 + 768) {
        int j = idx - total_u32;
        float4 v = make_float4(0.f, 0.f, 0.f, 0.f);
        if (j < 256)      { v.x = Wf11[j * 2];        v.y = Wf11[j * 2 + 1]; }
        else if (j < 512) { int q = j - 256;
                            v.x = Wf21[q * 4]; v.y = Wf21[q * 4 + 1];
                            v.z = Wf21[q * 4 + 2]; v.w = Wf21[q * 4 + 3]; }
        else              { int q = j - 512;
                            v.x = Wh1[q * 2];  v.y = Wh1[q * 2 + 1]; }
        g_smallW4[j] = v;
    }
}

// ---------------------------------------------------------------------------
__device__ __forceinline__ void mma16816(float* d, const unsigned* a, uint2 b) {
    asm volatile(
        "mma.sync.aligned.m16n8k16.row.col.f32.bf16.bf16.f32 "
        "{%0,%1,%2,%3}, {%4,%5,%6,%7}, {%8,%9}, {%0,%1,%2,%3};\n"
        : "+f"(d[0]), "+f"(d[1]), "+f"(d[2]), "+f"(d[3])
        : "r"(a[0]), "r"(a[1]), "r"(a[2]), "r"(a[3]), "r"(b.x), "r"(b.y));
}
__device__ __forceinline__ void ldmA(unsigned* a, unsigned addr) {
    asm volatile(
        "ldmatrix.sync.aligned.m8n8.x4.shared.b16 {%0,%1,%2,%3}, [%4];\n"
        : "=r"(a[0]), "=r"(a[1]), "=r"(a[2]), "=r"(a[3]) : "r"(addr));
}
__device__ __forceinline__ float tanha(float x) {
    float y; asm("tanh.approx.f32 %0, %1;" : "=f"(y) : "f"(x)); return y;
}

// M=16 GEMM over NT contiguous tiles (tile i at wb + i*KSTEPS*32).
// FULLY UNROLLED k-loop: all register-array indices are compile-time.
// 2-slot B buffer, prefetch distance 2; ping-pong A ldmatrix distance 1.
// Last NG3 tiles skip the final kstep.
template <int NT, int NG3>
__device__ __forceinline__ void run_gemm(const uint2* __restrict__ wb,
                                         unsigned abase, float (&D)[NT][4]) {
    unsigned a[2][4];
    uint2 b[NT][2];
#pragma unroll
    for (int i = 0; i < NT; i++) {
        b[i][0] = wb[(i * KSTEPS + 0) * 32];
        b[i][1] = wb[(i * KSTEPS + 1) * 32];
    }
    ldmA(a[0], abase);
#pragma unroll
    for (int ks = 0; ks < KSTEPS; ks++) {
        if (ks + 1 < KSTEPS)
            ldmA(a[(ks + 1) & 1], abase + (unsigned)(ks + 1) * 32u);
#pragma unroll
        for (int i = 0; i < NT; i++) {
            if (i < NT - NG3 || ks < KSTEPS - 1)
                mma16816(D[i], a[ks & 1], b[i][ks & 1]);
            if (ks + 2 < KSTEPS)
                b[i][ks & 1] = wb[(i * KSTEPS + ks + 2) * 32];
        }
    }
}

__device__ __forceinline__ void write_act_tanh(int ntile, int cbase, int row0,
        const float (&D)[4], const float* __restrict__ bias,
        __nv_bfloat16 (*actp)[ACT_STRIDE]) {
    int col = ntile * 8 + cbase;
    float bv0 = bias[col], bv1 = bias[col + 1];
    __nv_bfloat162 h0, h1;
    h0.x = __float2bfloat16(tanha(D[0] + bv0));
    h0.y = __float2bfloat16(tanha(D[1] + bv1));
    h1.x = __float2bfloat16(tanha(D[2] + bv0));
    h1.y = __float2bfloat16(tanha(D[3] + bv1));
    *reinterpret_cast<__nv_bfloat162*>(&actp[row0][col]) = h0;
    *reinterpret_cast<__nv_bfloat162*>(&actp[row0 + 8][col]) = h1;
}

__device__ __forceinline__ void g2_epilogue(int tg, int cbase,
        const float (&D)[4], const float* __restrict__ bias2s,
        const float4* __restrict__ smallWs, float (&o)[2][8]) {
    int col = tg * 8 + cbase;
    int seg = tg >> 5;  // 0: Wf11 (d), 1: Wf21 (pv), 2: Wh1 (hv)
    float bb0 = bias2s[col], bb1 = bias2s[col + 1];
    float4 w0 = smallWs[col];
    float4 w1 = smallWs[col + 1];
    int ob = (seg == 0) ? 0 : ((seg == 1) ? 2 : 6);
    float h0 = tanha(D[0] + bb0);
    float h1 = tanha(D[1] + bb1);
    float h2 = tanha(D[2] + bb0);
    float h3 = tanha(D[3] + bb1);
    o[0][ob + 0] += h0 * w0.x + h1 * w1.x;
    o[0][ob + 1] += h0 * w0.y + h1 * w1.y;
    o[1][ob + 0] += h2 * w0.x + h3 * w1.x;
    o[1][ob + 1] += h2 * w0.y + h3 * w1.y;
    if (seg == 1) {
        o[0][ob + 2] += h0 * w0.z + h1 * w1.z;
        o[0][ob + 3] += h0 * w0.w + h1 * w1.w;
        o[1][ob + 2] += h2 * w0.z + h3 * w1.z;
        o[1][ob + 3] += h2 * w0.w + h3 * w1.w;
    }
}

// ---------------------------------------------------------------------------
// Main persistent kernel: 128 CTAs x 512 threads, 16 batch rows per CTA.
// ---------------------------------------------------------------------------
__global__ void __launch_bounds__(NTHREADS, 1) egbrnn_main(
    const float* __restrict__ x, const float* __restrict__ target,
    const float* __restrict__ c0,
    const float* __restrict__ bm0, const float* __restrict__ bm1,
    const float* __restrict__ bf10, const float* __restrict__ bf11,
    const float* __restrict__ bf20, const float* __restrict__ bf21,
    const float* __restrict__ bh0, const float* __restrict__ bh1,
    float* __restrict__ out)
{
    __shared__ __align__(16) __nv_bfloat16 act[MCTA][ACT_STRIDE];
    __shared__ float sS[MCTA][4];
    __shared__ float Pm[MCTA][16];
    __shared__ float measS[MCTA][2];
    __shared__ float part[NWARPS][MCTA][9];
    __shared__ float bm0s[256], bm1s[256], bias2s[768], biasSs[8];
    __shared__ __align__(16) float4 smallWs[768];

    const int tid = threadIdx.x;
    const int w = tid >> 5, lane = tid & 31;
    const int b0 = blockIdx.x * MCTA;
    const int row0 = lane >> 2;
    const int cbase = (lane & 3) * 2;

    // ---- one-time shared init ----
    if (tid < 256) { bm0s[tid] = bm0[tid]; bm1s[tid] = bm1[tid]; }
    for (int i = tid; i < 768; i += NTHREADS) {
        bias2s[i] = (i < 256) ? bf10[i] : (i < 512 ? bf20[i - 256] : bh0[i - 512]);
        smallWs[i] = g_smallW4[i];
    }
    if (tid < 8)
        biasSs[tid] = (tid < 2) ? bf11[tid] : (tid < 6 ? bf21[tid - 2] : bh1[tid - 6]);
    for (int i = tid; i < MCTA * 24; i += NTHREADS) {   // zero cols 256..279
        int r = i / 24, c = 256 + i % 24;
        act[r][c] = __float2bfloat16(0.f);
    }
    for (int i = tid; i < MCTA * 256; i += NTHREADS) {  // c = c0
        int r = i >> 8, j = i & 255;
        act[r][j] = __float2bfloat16(c0[(size_t)(b0 + r) * 256 + j]);
    }
    __syncthreads();
    if (tid < MCTA) {
        int r = tid;
        float4 tg = *reinterpret_cast<const float4*>(
            &target[((size_t)(b0 + r) * T_STEPS) * 4]);
        sS[r][0] = tg.x; sS[r][1] = tg.y; sS[r][2] = tg.z; sS[r][3] = tg.w;
#pragma unroll
        for (int i = 0; i < 16; i++) Pm[r][i] = (i % 5 == 0) ? 1.f : 0.f;
        __nv_bfloat162 a01, a23;
        a01.x = __float2bfloat16(tg.x * (1.f / 60.f));
        a01.y = __float2bfloat16(tg.y * (1.f / 60.f));
        a23.x = __float2bfloat16(tg.z * (1.f / 60.f));
        a23.y = __float2bfloat16(tg.w * (1.f / 60.f));
        *reinterpret_cast<__nv_bfloat162*>(&act[r][258]) = a01;  // s/60
        *reinterpret_cast<__nv_bfloat162*>(&act[r][260]) = a23;
    }
    __syncthreads();

    const unsigned ab0 =
        (unsigned)__cvta_generic_to_shared(&act[lane & 15][(lane >> 4) * 8]);
    const uint2* wG1 = g_Wpk + (2 * w) * KSTEPS * 32 + lane;
    const uint2* wP3 = g_Wpk + (32 + 8 * w) * KSTEPS * 32 + lane;

    for (int t = 0; t < T_STEPS; t++) {
        // ---- P1: GEMM1 (cu preactivation), 2 tiles/warp ----
        float D1[2][4];
#pragma unroll
        for (int i = 0; i < 2; i++)
            D1[i][0] = D1[i][1] = D1[i][2] = D1[i][3] = 0.f;
        run_gemm<2, 0>(wG1, ab0, D1);
        __syncthreads();

        // ---- P2: write cu over c; load meas; write m2 ----
        write_act_tanh(2 * w,     cbase, row0, D1[0], bm0s, act);
        write_act_tanh(2 * w + 1, cbase, row0, D1[1], bm0s, act);
        if (tid < MCTA) {
            int r = tid;
            float2 m = *reinterpret_cast<const float2*>(
                &x[(((size_t)(b0 + r)) * T_STEPS + t) * 2]);
            measS[r][0] = m.x; measS[r][1] = m.y;
            __nv_bfloat162 mm;
            mm.x = __float2bfloat16(m.x * (1.f / 60.f));
            mm.y = __float2bfloat16(m.y * (1.f / 60.f));
            *reinterpret_cast<__nv_bfloat162*>(&act[r][256]) = mm;
        }
        __syncthreads();

        // ---- P3: fused GEMM2 (6 tiles) + GEMM3 ks 0..15 (2 tiles) ----
        uint2 b3l[2];
        b3l[0] = wP3[(6 * KSTEPS + 16) * 32];
        b3l[1] = wP3[(7 * KSTEPS + 16) * 32];
        float D2[8][4];
#pragma unroll
        for (int i = 0; i < 8; i++)
            D2[i][0] = D2[i][1] = D2[i][2] = D2[i][3] = 0.f;
        run_gemm<8, 2>(wP3, ab0, D2);
        float o[2][8];
#pragma unroll
        for (int s = 0; s < 2; s++)
#pragma unroll
            for (int k = 0; k < 8; k++) o[s][k] = 0.f;
#pragma unroll
        for (int j = 0; j < 6; j++)
            g2_epilogue(6 * w + j, cbase, D2[j], bias2s, smallWs, o);
#pragma unroll
        for (int s = 0; s < 2; s++)
#pragma unroll
            for (int k = 0; k < 8; k++) {
                o[s][k] += __shfl_xor_sync(0xffffffffu, o[s][k], 1);
                o[s][k] += __shfl_xor_sync(0xffffffffu, o[s][k], 2);
            }
        if ((lane & 3) == 0) {
#pragma unroll
            for (int k = 0; k < 8; k++) {
                part[w][row0][k]     = o[0][k];
                part[w][row0 + 8][k] = o[1][k];
            }
        }
        __syncthreads();

        // ---- P4: per-row Kalman update (fp32) ----
        if (tid < MCTA) {
            const int r = tid;
            float sm[8];
#pragma unroll
            for (int k = 0; k < 8; k++) {
                float a = biasSs[k];
#pragma unroll
                for (int ww = 0; ww < NWARPS; ww++) a += part[ww][r][k];
                sm[k] = a;
            }
            const float d0 = sm[0], d1 = sm[1];
            const float pv[4] = {sm[2], sm[3], sm[4], sm[5]};
            const float hv0 = sm[6], hv1 = sm[7];
            float s0 = sS[r][0], s1 = sS[r][1], s2 = sS[r][2], s3 = sS[r][3];
            float sp[4];
            sp[0] = s0 + s2 + 0.5f * d0;
            sp[1] = s1 + s3 + 0.5f * d1;
            sp[2] = s2 + d0;
            sp[3] = s3 + d1;
            float P[4][4];
#pragma unroll
            for (int i = 0; i < 4; i++)
#pragma unroll
                for (int j = 0; j < 4; j++) P[i][j] = Pm[r][i * 4 + j];
            float FP[4][4], Pp[4][4];
#pragma unroll
            for (int j = 0; j < 4; j++) {
                FP[0][j] = P[0][j] + P[2][j];
                FP[1][j] = P[1][j] + P[3][j];
                FP[2][j] = P[2][j];
                FP[3][j] = P[3][j];
            }
#pragma unroll
            for (int i = 0; i < 4; i++) {
                Pp[i][0] = FP[i][0] + FP[i][2];
                Pp[i][1] = FP[i][1] + FP[i][3];
                Pp[i][2] = FP[i][2];
                Pp[i][3] = FP[i][3];
            }
#pragma unroll
            for (int i = 0; i < 4; i++)
#pragma unroll
                for (int j = 0; j < 4; j++) Pp[i][j] += pv[i] * pv[j];
#pragma unroll
            for (int i = 0; i < 4; i++) Pp[i][i] += 0.01f;
            float m0 = measS[r][0], m1 = measS[r][1];
            float in0 = m0 - sp[0], in1 = m1 - sp[1];
            float S00 = Pp[0][0] + hv0 * hv0 + 1.f;
            float S01 = Pp[0][1] + hv0 * hv1;
            float S10 = Pp[1][0] + hv1 * hv0;
            float S11 = Pp[1][1] + hv1 * hv1 + 1.f;
            float inv = 1.0f / (S00 * S11 - S01 * S10);
            float K[4][2], KS[4][2], su[4];
#pragma unroll
            for (int i = 0; i < 4; i++) {
                K[i][0] = (Pp[i][0] * S11 - Pp[i][1] * S10) * inv;
                K[i][1] = (Pp[i][1] * S00 - Pp[i][0] * S01) * inv;
                su[i] = sp[i] + K[i][0] * in0 + K[i][1] * in1;
                KS[i][0] = K[i][0] * S00 + K[i][1] * S10;
                KS[i][1] = K[i][0] * S01 + K[i][1] * S11;
            }
#pragma unroll
            for (int i = 0; i < 4; i++)
#pragma unroll
                for (int j = 0; j < 4; j++)
                    Pm[r][i * 4 + j] =
                        Pp[i][j] - KS[i][0] * K[j][0] - KS[i][1] * K[j][1];
            sS[r][0] = su[0]; sS[r][1] = su[1];
            sS[r][2] = su[2]; sS[r][3] = su[3];
            float4 ov = make_float4(su[0], su[1], su[2], su[3]);
            *reinterpret_cast<float4*>(
                &out[(((size_t)(b0 + r)) * T_STEPS + t) * 4]) = ov;
            __nv_bfloat162 q0, q1;
            q0.x = __float2bfloat16(su[0] * (1.f / 60.f));
            q0.y = __float2bfloat16(su[1] * (1.f / 60.f));
            q1.x = __float2bfloat16(su[2] * (1.f / 60.f));
            q1.y = __float2bfloat16(su[3] * (1.f / 60.f));
            *reinterpret_cast<__nv_bfloat162*>(&act[r][258]) = q0;  // su/60 == next sn
            *reinterpret_cast<__nv_bfloat162*>(&act[r][260]) = q1;
        }
        __syncthreads();

        // ---- P5: GEMM3 final kstep (reads tail cols 256..271) + c_new.
        //      Reads only cols 256..271, writes only cols 0..255: disjoint. ----
        {
            unsigned a0[4];
            ldmA(a0, ab0 + 16u * 32u);
            mma16816(D2[6], a0, b3l[0]);
            mma16816(D2[7], a0, b3l[1]);
        }
        write_act_tanh(2 * w,     cbase, row0, D2[6], bm1s, act);
        write_act_tanh(2 * w + 1, cbase, row0, D2[7], bm1s, act);
        __syncthreads();
    }
}

// ---------------------------------------------------------------------------
extern "C" void kernel_launch(void* const* d_in, const int* in_sizes, int n_in,
                              void* d_out, int out_size)
{
    const float* x    = (const float*)d_in[0];
    const float* targ = (const float*)d_in[1];
    const float* c0   = (const float*)d_in[2];
    const float* Wm0  = (const float*)d_in[3];
    const float* bm0  = (const float*)d_in[4];
    const float* Wm1  = (const float*)d_in[5];
    const float* bm1  = (const float*)d_in[6];
    const float* Wf10 = (const float*)d_in[7];
    const float* bf10 = (const float*)d_in[8];
    const float* Wf11 = (const float*)d_in[9];
    const float* bf11 = (const float*)d_in[10];
    const float* Wf20 = (const float*)d_in[11];
    const float* bf20 = (const float*)d_in[12];
    const float* Wf21 = (const float*)d_in[13];
    const float* bf21 = (const float*)d_in[14];
    const float* Wh0  = (const float*)d_in[15];
    const float* bh0  = (const float*)d_in[16];
    const float* Wh1  = (const float*)d_in[17];
    const float* bh1  = (const float*)d_in[18];
    float* out = (float*)d_out;

    const int tot = 160 * 17 * 32 * 2 + 768;
    prepack_kernel<<<(tot + 255) / 256, 256>>>(Wm0, Wf10, Wf20, Wh0, Wm1,
                                               Wf11, Wf21, Wh1);
    egbrnn_main<<<NCTAS, NTHREADS>>>(x, targ, c0, bm0, bm1, bf10, bf11,
                                     bf20, bf21, bh0, bh1, out);
}